// round 1
// baseline (speedup 1.0000x reference)
#include <cuda_runtime.h>
#include <cstdint>

// Problem constants (fixed shapes from reference)
#define Bc    128
#define Nc    512
#define Kc    12
#define DIMc  128
#define BN_TOTAL (Bc * Nc)
#define BN_PER   32          // bn handled per block in kernel1

// Scratch for aggregated neighbor features [B*N, DIM] (no cudaMalloc allowed)
__device__ float g_agg[(size_t)BN_TOTAL * DIMc];

// ---------- packed fp32x2 helpers ----------
__device__ __forceinline__ unsigned long long dup2(float s) {
    unsigned long long r;
    asm("mov.b64 %0, {%1, %1};" : "=l"(r) : "f"(s));
    return r;
}
__device__ __forceinline__ unsigned long long fma2(unsigned long long a,
                                                   unsigned long long b,
                                                   unsigned long long c) {
    unsigned long long d;
    asm("fma.rn.f32x2 %0, %1, %2, %3;" : "=l"(d) : "l"(a), "l"(b), "l"(c));
    return d;
}
__device__ __forceinline__ void unpack2(unsigned long long v, float& lo, float& hi) {
    asm("mov.b64 {%0, %1}, %2;" : "=f"(lo), "=f"(hi) : "l"(v));
}

// =====================================================================
// Kernel 1: attention scores + softmax + neighbor aggregation
//   block = 128 threads (one thread per output dim d), handles BN_PER bn's.
//   Thread d holds W1 column d (130 entries, rows 0..128 real, 129 zero pad)
//   in registers. en[j][k] = extra[j]*nbr[k][j] (j=128 row = edge weight,
//   j=129 = zero pad) staged in smem with interleaved layout:
//     float idx(k,j) = ((k>>1)*65 + (j>>1))*4 + (j&1)*2 + (k&1)
//   so one 16B broadcast load feeds 2 fma.f32x2 (k-pair x j-pair).
// =====================================================================
__global__ __launch_bounds__(128)
void attn_kernel(const float* __restrict__ nbrv,   // [B,N,K,DIM]
                 const float* __restrict__ nbrw,   // [B,N,K]
                 const float* __restrict__ extra,  // [B,N,DIM]
                 const float* __restrict__ w1,     // [129,128]
                 const float* __restrict__ w2)     // [128,1]
{
    __shared__ __align__(16) float en_s[6 * 65 * 4];   // 6.2 KB
    __shared__ float nbr_s[Kc][DIMc];                  // 6 KB
    __shared__ float extra_s[DIMc];
    __shared__ float wgt_s[Kc];
    __shared__ float red_s[4][Kc];

    const int t = threadIdx.x;
    const int warp = t >> 5, lane = t & 31;

    // W1 column for this thread (registers), plus w2 scalar
    float w1c[130];
#pragma unroll
    for (int f = 0; f < 129; f++) w1c[f] = w1[f * DIMc + t];
    w1c[129] = 0.f;
    const float w2d = w2[t];

    const int bn0 = blockIdx.x * BN_PER;
    for (int i = 0; i < BN_PER; i++) {
        const int bn = bn0 + i;

        // ---- stage inputs ----
        const float* nb = nbrv + (size_t)bn * Kc * DIMc;
#pragma unroll
        for (int k = 0; k < Kc; k++) nbr_s[k][t] = nb[k * DIMc + t];
        extra_s[t] = extra[(size_t)bn * DIMc + t];
        if (t < Kc) wgt_s[t] = nbrw[(size_t)bn * Kc + t];
        __syncthreads();

        // ---- en precompute: thread t handles j=t; t==0 does j=128,129 ----
        {
            const float e = extra_s[t];
#pragma unroll
            for (int k = 0; k < Kc; k++) {
                float v = e * nbr_s[k][t];
                int idx = (((k >> 1) * 65 + (t >> 1)) << 2) + ((t & 1) << 1) + (k & 1);
                en_s[idx] = v;
            }
            if (t == 0) {
#pragma unroll
                for (int k = 0; k < Kc; k++) {
                    int base = (((k >> 1) * 65 + 64) << 2) + (k & 1);
                    en_s[base]     = wgt_s[k]; // j=128: the edge-weight column
                    en_s[base + 2] = 0.f;      // j=129: zero pad
                }
            }
        }
        __syncthreads();

        // ---- main GEMM: alpha[k,d] = sum_j en[j][k] * w1c[j] ----
        unsigned long long acc[6];
#pragma unroll
        for (int kk = 0; kk < 6; kk++) acc[kk] = 0ull;
        const ulonglong2* en2 = reinterpret_cast<const ulonglong2*>(en_s);
#pragma unroll
        for (int jp = 0; jp < 65; jp++) {
            unsigned long long wa = dup2(w1c[2 * jp]);
            unsigned long long wb = dup2(w1c[2 * jp + 1]);
#pragma unroll
            for (int kk = 0; kk < 6; kk++) {
                ulonglong2 v = en2[kk * 65 + jp];
                acc[kk] = fma2(v.x, wa, acc[kk]);
                acc[kk] = fma2(v.y, wb, acc[kk]);
            }
        }

        // ---- leaky_relu, * w2[d], reduce over d ----
        float p[Kc];
#pragma unroll
        for (int kk = 0; kk < 6; kk++) {
            float a0, a1;
            unpack2(acc[kk], a0, a1);
            a0 = (a0 > 0.f) ? a0 : 0.2f * a0;
            a1 = (a1 > 0.f) ? a1 : 0.2f * a1;
            p[2 * kk]     = a0 * w2d;
            p[2 * kk + 1] = a1 * w2d;
        }
#pragma unroll
        for (int off = 16; off > 0; off >>= 1) {
#pragma unroll
            for (int k = 0; k < Kc; k++)
                p[k] += __shfl_xor_sync(0xffffffffu, p[k], off);
        }
        if (lane == 0) {
#pragma unroll
            for (int k = 0; k < Kc; k++) red_s[warp][k] = p[k];
        }
        __syncthreads();

        // ---- softmax over K (all threads redundantly) ----
        float sc[Kc];
        float m = -1e30f;
#pragma unroll
        for (int k = 0; k < Kc; k++) {
            sc[k] = red_s[0][k] + red_s[1][k] + red_s[2][k] + red_s[3][k];
            m = fmaxf(m, sc[k]);
        }
        float ssum = 0.f;
#pragma unroll
        for (int k = 0; k < Kc; k++) { sc[k] = __expf(sc[k] - m); ssum += sc[k]; }
        const float inv = 1.0f / ssum;

        // ---- aggregate: agg[d] = sum_k alpha_k * nbr[k][d] ----
        float a = 0.f;
#pragma unroll
        for (int k = 0; k < Kc; k++) a = fmaf(sc[k], nbr_s[k][t], a);
        g_agg[(size_t)bn * DIMc + t] = a * inv;

        __syncthreads();   // protect smem before next iteration's loads
    }
}

// =====================================================================
// Kernel 2: out[bn,:] = relu(concat(self[bn], agg[bn]) @ W3), W3 [256,128]
//   W3 resident in dynamic smem (128 KB). 256 threads; per iteration the
//   block processes 8 bn rows: thread t -> row r=t>>5, cols 4*(t&31)..+3.
// =====================================================================
__global__ __launch_bounds__(256)
void out_kernel(const float* __restrict__ selfv,  // [B,N,DIM]
                const float* __restrict__ w3,     // [256,128]
                float* __restrict__ out)          // [B,N,DIM]
{
    extern __shared__ __align__(16) float smem[];
    float* W3s = smem;               // 256*128
    float* xs  = smem + 256 * 128;   // 8*256

    const int t = threadIdx.x;
    for (int idx = t; idx < 256 * 128; idx += 256) W3s[idx] = w3[idx];

    const int r  = t >> 5;
    const int c4 = (t & 31) << 2;

    for (int it = blockIdx.x; it < BN_TOTAL / 8; it += gridDim.x) {
        const int bn0 = it * 8;
        // stage x = concat(self, agg) for 8 rows
        for (int idx = t; idx < 8 * 256; idx += 256) {
            int rr = idx >> 8, f = idx & 255;
            xs[idx] = (f < 128) ? selfv[(size_t)(bn0 + rr) * 128 + f]
                                : g_agg[(size_t)(bn0 + rr) * 128 + (f - 128)];
        }
        __syncthreads();   // also fences W3s on first iteration

        const float* xr = xs + (r << 8);
        unsigned long long acc0 = 0ull, acc1 = 0ull;
#pragma unroll 4
        for (int f = 0; f < 256; f += 4) {
            float4 xv = *reinterpret_cast<const float4*>(xr + f);
#pragma unroll
            for (int q = 0; q < 4; q++) {
                float xf = (q == 0) ? xv.x : (q == 1) ? xv.y : (q == 2) ? xv.z : xv.w;
                unsigned long long xx = dup2(xf);
                ulonglong2 wv = *reinterpret_cast<const ulonglong2*>(W3s + (f + q) * 128 + c4);
                acc0 = fma2(xx, wv.x, acc0);
                acc1 = fma2(xx, wv.y, acc1);
            }
        }
        float o0, o1, o2, o3;
        unpack2(acc0, o0, o1);
        unpack2(acc1, o2, o3);
        float4 ov = make_float4(fmaxf(o0, 0.f), fmaxf(o1, 0.f),
                                fmaxf(o2, 0.f), fmaxf(o3, 0.f));
        *reinterpret_cast<float4*>(out + (size_t)(bn0 + r) * 128 + c4) = ov;
        __syncthreads();   // xs reuse
    }
}

// =====================================================================
// Launch
// Inputs (metadata order): 0 self_vectors, 1 neighbor_vector,
//   2 neighbor_weight, 3 extra_vector, 4 masks, 5 batch_size,
//   6 w_1, 7 w_2, 8 w_3
// =====================================================================
extern "C" void kernel_launch(void* const* d_in, const int* in_sizes, int n_in,
                              void* d_out, int out_size)
{
    const float* selfv = (const float*)d_in[0];
    const float* nbrv  = (const float*)d_in[1];
    const float* nbrw  = (const float*)d_in[2];
    const float* extra = (const float*)d_in[3];
    const float* w1    = (const float*)d_in[6];
    const float* w2    = (const float*)d_in[7];
    const float* w3    = (const float*)d_in[8];
    float* out = (float*)d_out;

    attn_kernel<<<BN_TOTAL / BN_PER, 128>>>(nbrv, nbrw, extra, w1, w2);

    const int smem_bytes = (256 * 128 + 8 * 256) * (int)sizeof(float);  // 139264
    cudaFuncSetAttribute(out_kernel, cudaFuncAttributeMaxDynamicSharedMemorySize,
                         smem_bytes);
    out_kernel<<<296, 256, smem_bytes>>>(selfv, w3, out);
}

// round 2
// speedup vs baseline: 1.2339x; 1.2339x over previous
#include <cuda_runtime.h>
#include <cstdint>

// Problem constants (fixed shapes)
#define Bc    128
#define Nc    512
#define Kc    12
#define DIMc  128
#define BN_TOTAL (Bc * Nc)
#define BN_PER   32

// Scratch for aggregated neighbor features [B*N, DIM]
__device__ __align__(16) float g_agg[(size_t)BN_TOTAL * DIMc];

// ---------- packed fp32x2 helpers (bit-exact: two fp32 FMAs) ----------
__device__ __forceinline__ unsigned long long dup2(float s) {
    unsigned long long r;
    asm("mov.b64 %0, {%1, %1};" : "=l"(r) : "f"(s));
    return r;
}
__device__ __forceinline__ unsigned long long pack2(float a, float b) {
    unsigned long long r;
    asm("mov.b64 %0, {%1, %2};" : "=l"(r) : "f"(a), "f"(b));
    return r;
}
__device__ __forceinline__ unsigned long long fma2(unsigned long long a,
                                                   unsigned long long b,
                                                   unsigned long long c) {
    unsigned long long d;
    asm("fma.rn.f32x2 %0, %1, %2, %3;" : "=l"(d) : "l"(a), "l"(b), "l"(c));
    return d;
}
__device__ __forceinline__ void unpack2(unsigned long long v, float& lo, float& hi) {
    asm("mov.b64 {%0, %1}, %2;" : "=f"(lo), "=f"(hi) : "l"(v));
}

// =====================================================================
// Kernel 1: attention scores + softmax + neighbor aggregation.
//   256 threads: d = t&127 (output dim), h = t>>7 (j-half).
//   Thread holds W1 rows j = h*66 .. h*66+65 for column d (66 regs;
//   rows 129..131 are zero pad). en[j][k] staged in smem interleaved:
//     idx(k,j) = ((k>>1)*66 + (j>>1))*4 + (j&1)*2 + (k&1)
//   so one broadcast LDS.128 feeds 2 fma.f32x2 (k-pair x j-pair).
//   Next-bn inputs are prefetched into registers under the GEMM.
// =====================================================================
__global__ __launch_bounds__(256, 2)
void attn_kernel(const float* __restrict__ nbrv,   // [B,N,K,DIM]
                 const float* __restrict__ nbrw,   // [B,N,K]
                 const float* __restrict__ extra,  // [B,N,DIM]
                 const float* __restrict__ w1,     // [129,128]
                 const float* __restrict__ w2)     // [128,1]
{
    __shared__ __align__(16) float en_s[6 * 66 * 4];          // 6.3 KB
    __shared__ float nbr_s[Kc][DIMc];                         // 6 KB
    __shared__ __align__(8) unsigned long long comb[128 * 7]; // 7 KB (pad 7 vs 6)
    __shared__ float red_s[4][Kc];

    const int t    = threadIdx.x;
    const int d    = t & 127;
    const int h    = t >> 7;          // 0 or 1
    const int warp = t >> 5, lane = t & 31;

    // W1 half-column in registers
    float w1c[66];
#pragma unroll
    for (int jl = 0; jl < 66; jl++) {
        int j = h * 66 + jl;
        w1c[jl] = (j <= 128) ? w1[j * DIMc + d] : 0.f;
    }
    const float w2d = w2[d];

    // zero en_s pad rows j=129,130,131 (never rewritten; w1c pad is 0 anyway,
    // but avoid reading uninitialized smem)
    if (t < Kc) {
        int kk = t >> 1, kb = t & 1;
        en_s[(kk * 66 + 64) * 4 + 2 + kb] = 0.f;  // j=129
        en_s[(kk * 66 + 65) * 4 + 0 + kb] = 0.f;  // j=130
        en_s[(kk * 66 + 65) * 4 + 2 + kb] = 0.f;  // j=131
    }

    const int bn0 = blockIdx.x * BN_PER;

    // prefetch iter 0: thread t holds nbr[k=2q+h][j=d] for q=0..5
    float nr[6], er, wr = 0.f;
    {
        const float* nb = nbrv + (size_t)bn0 * Kc * DIMc;
#pragma unroll
        for (int q = 0; q < 6; q++) nr[q] = nb[t + q * 256];
        er = extra[(size_t)bn0 * DIMc + d];
        if (t < Kc) wr = nbrw[(size_t)bn0 * Kc + t];
    }

    for (int i = 0; i < BN_PER; i++) {
        const int bn = bn0 + i;

        __syncthreads();   // A: previous iteration's readers are done
        // ---- store staged regs: nbr tile + en entries ----
#pragma unroll
        for (int q = 0; q < 6; q++) {
            int k = 2 * q + h;
            nbr_s[k][d] = nr[q];
            int idx = (((k >> 1) * 66 + (d >> 1)) << 2) + ((d & 1) << 1) + (k & 1);
            en_s[idx] = er * nr[q];
        }
        if (t < Kc) {
            int kk = t >> 1, kb = t & 1;
            en_s[(kk * 66 + 64) * 4 + kb] = wr;   // j=128: edge weight row
        }
        __syncthreads();   // B: en_s/nbr_s visible

        // ---- prefetch next bn (hidden under GEMM) ----
        if (i + 1 < BN_PER) {
            const int bn1 = bn + 1;
            const float* nb = nbrv + (size_t)bn1 * Kc * DIMc;
#pragma unroll
            for (int q = 0; q < 6; q++) nr[q] = nb[t + q * 256];
            er = extra[(size_t)bn1 * DIMc + d];
            if (t < Kc) wr = nbrw[(size_t)bn1 * Kc + t];
        }

        // ---- GEMM half: acc[kk] += en[j-pair, k-pair] * w1c[j-pair] ----
        unsigned long long acc[6];
#pragma unroll
        for (int kk = 0; kk < 6; kk++) acc[kk] = 0ull;
        const ulonglong2* en2 = reinterpret_cast<const ulonglong2*>(en_s);
        const int jbase = h * 33;
#pragma unroll
        for (int jp = 0; jp < 33; jp++) {
            unsigned long long wa = dup2(w1c[2 * jp]);
            unsigned long long wb = dup2(w1c[2 * jp + 1]);
#pragma unroll
            for (int kk = 0; kk < 6; kk++) {
                ulonglong2 v = en2[kk * 66 + jbase + jp];
                acc[kk] = fma2(v.x, wa, acc[kk]);
                acc[kk] = fma2(v.y, wb, acc[kk]);
            }
        }

        // ---- combine halves: h=1 stores partials, h=0 finishes ----
        if (h == 1) {
#pragma unroll
            for (int kk = 0; kk < 6; kk++) comb[d * 7 + kk] = acc[kk];
        }
        __syncthreads();   // C

        if (h == 0) {
            float p[Kc];
#pragma unroll
            for (int kk = 0; kk < 6; kk++) {
                float c0, c1, a0, a1;
                unpack2(comb[d * 7 + kk], c0, c1);
                unpack2(acc[kk], a0, a1);
                a0 += c0; a1 += c1;
                a0 = (a0 > 0.f) ? a0 : 0.2f * a0;
                a1 = (a1 > 0.f) ? a1 : 0.2f * a1;
                p[2 * kk]     = a0 * w2d;
                p[2 * kk + 1] = a1 * w2d;
            }
#pragma unroll
            for (int off = 16; off > 0; off >>= 1) {
#pragma unroll
                for (int k = 0; k < Kc; k++)
                    p[k] += __shfl_xor_sync(0xffffffffu, p[k], off);
            }
            if (lane == 0) {
#pragma unroll
                for (int k = 0; k < Kc; k++) red_s[warp][k] = p[k];
            }
        }
        __syncthreads();   // D

        // ---- softmax (redundant across threads) + aggregation ----
        float sc[Kc];
        float m = -1e30f;
#pragma unroll
        for (int k = 0; k < Kc; k++) {
            sc[k] = red_s[0][k] + red_s[1][k] + red_s[2][k] + red_s[3][k];
            m = fmaxf(m, sc[k]);
        }
        float ssum = 0.f;
#pragma unroll
        for (int k = 0; k < Kc; k++) { sc[k] = __expf(sc[k] - m); ssum += sc[k]; }
        const float inv = 1.0f / ssum;

        if (h == 0) {
            float a = 0.f;
#pragma unroll
            for (int k = 0; k < Kc; k++) a = fmaf(sc[k], nbr_s[k][d], a);
            g_agg[(size_t)bn * DIMc + d] = a * inv;
        }
    }
}

// =====================================================================
// Kernel 2: out = relu(concat(self, agg) @ W3), W3 [256,128].
//   512 threads: c = t&127 (output col), h = t>>7 (f-quarter, 64 rows).
//   W3 quarter-column lives in REGISTERS as 32 packed f32x2 pairs;
//   x rows are broadcast from smem (1 crossbar cyc per LDS.128).
//   16 rows per epoch; 4 partials combined via stride-5 padded smem.
// =====================================================================
#define OUT_ROWS 16
__global__ __launch_bounds__(512, 1)
void out_kernel(const float* __restrict__ selfv,  // [B,N,DIM]
                const float* __restrict__ w3,     // [256,128]
                float* __restrict__ out)          // [B,N,DIM]
{
    extern __shared__ __align__(16) float sm[];
    float* xs = sm;                      // [16][256]
    float* ps = sm + OUT_ROWS * 256;     // [16][128][5] (pad 5 -> conflict-free)

    const int t = threadIdx.x;
    const int c = t & 127;
    const int h = t >> 7;                // 0..3

    // W3 quarter-column: rows f = h*64 .. h*64+63, packed in f-pairs
    unsigned long long w3r[32];
#pragma unroll
    for (int q = 0; q < 32; q++) {
        int f = h * 64 + 2 * q;
        w3r[q] = pack2(w3[f * 128 + c], w3[(f + 1) * 128 + c]);
    }

    const int warp = t >> 5, lane = t & 31;
    const int n_epochs = BN_TOTAL / OUT_ROWS;   // 4096

    for (int e = blockIdx.x; e < n_epochs; e += gridDim.x) {
        const int row0 = e * OUT_ROWS;

        __syncthreads();   // protect xs/ps from previous epoch
        // ---- stage x = concat(self, agg) for 16 rows (2 float4 per thread) ----
#pragma unroll
        for (int v = 0; v < 2; v++) {
            int idx = t + v * 512;       // float4 index, 1024 total
            int row = idx >> 6;
            int f4  = idx & 63;
            const float* src = (f4 < 32)
                ? (selfv + (size_t)(row0 + row) * 128 + f4 * 4)
                : (g_agg + (size_t)(row0 + row) * 128 + (f4 - 32) * 4);
            reinterpret_cast<float4*>(xs)[idx] =
                *reinterpret_cast<const float4*>(src);
        }
        __syncthreads();

        // ---- per-row quarter dot products ----
#pragma unroll
        for (int row = 0; row < OUT_ROWS; row++) {
            const ulonglong2* xr =
                reinterpret_cast<const ulonglong2*>(xs + row * 256 + h * 64);
            unsigned long long acc0 = 0ull, acc1 = 0ull;
#pragma unroll
            for (int q = 0; q < 16; q++) {
                ulonglong2 xv = xr[q];                 // broadcast within warp
                acc0 = fma2(xv.x, w3r[2 * q],     acc0);
                acc1 = fma2(xv.y, w3r[2 * q + 1], acc1);
            }
            float a0, a1, b0, b1;
            unpack2(acc0, a0, a1);
            unpack2(acc1, b0, b1);
            ps[(row * 128 + c) * 5 + h] = (a0 + a1) + (b0 + b1);
        }
        __syncthreads();

        // ---- finalize: warp w handles row w, lane covers 4 columns ----
        {
            const int row = warp;
            float* pr = ps + row * 128 * 5;
#pragma unroll
            for (int iq = 0; iq < 4; iq++) {
                int cc = lane + 32 * iq;
                float s = pr[cc * 5 + 0] + pr[cc * 5 + 1]
                        + pr[cc * 5 + 2] + pr[cc * 5 + 3];
                out[(size_t)(row0 + row) * 128 + cc] = fmaxf(s, 0.f);
            }
        }
    }
}

// =====================================================================
// Launch.  Inputs (metadata order): 0 self_vectors, 1 neighbor_vector,
//   2 neighbor_weight, 3 extra_vector, 4 masks, 5 batch_size,
//   6 w_1, 7 w_2, 8 w_3
// =====================================================================
extern "C" void kernel_launch(void* const* d_in, const int* in_sizes, int n_in,
                              void* d_out, int out_size)
{
    const float* selfv = (const float*)d_in[0];
    const float* nbrv  = (const float*)d_in[1];
    const float* nbrw  = (const float*)d_in[2];
    const float* extra = (const float*)d_in[3];
    const float* w1    = (const float*)d_in[6];
    const float* w2    = (const float*)d_in[7];
    const float* w3    = (const float*)d_in[8];
    float* out = (float*)d_out;

    attn_kernel<<<BN_TOTAL / BN_PER, 256>>>(nbrv, nbrw, extra, w1, w2);

    const int smem_bytes = (OUT_ROWS * 256 + OUT_ROWS * 128 * 5) * (int)sizeof(float); // 57344
    cudaFuncSetAttribute(out_kernel, cudaFuncAttributeMaxDynamicSharedMemorySize,
                         smem_bytes);
    out_kernel<<<148, 512, smem_bytes>>>(selfv, w3, out);
}

// round 4
// speedup vs baseline: 3.0859x; 2.5008x over previous
#include <cuda_runtime.h>
#include <cuda_bf16.h>
#include <cstdint>

// Problem constants (fixed shapes)
#define Bc    128
#define Nc    512
#define Kc    12
#define DIMc  128
#define BN_TOTAL (Bc * Nc)

// Scratch for aggregated neighbor features [B*N, DIM]
__device__ __align__(16) float g_agg[(size_t)BN_TOTAL * DIMc];

// ---------- packed fp32x2 helpers (out_kernel) ----------
__device__ __forceinline__ unsigned long long dup2(float s) {
    unsigned long long r;
    asm("mov.b64 %0, {%1, %1};" : "=l"(r) : "f"(s));
    return r;
}
__device__ __forceinline__ unsigned long long pack2(float a, float b) {
    unsigned long long r;
    asm("mov.b64 %0, {%1, %2};" : "=l"(r) : "f"(a), "f"(b));
    return r;
}
__device__ __forceinline__ unsigned long long fma2(unsigned long long a,
                                                   unsigned long long b,
                                                   unsigned long long c) {
    unsigned long long d;
    asm("fma.rn.f32x2 %0, %1, %2, %3;" : "=l"(d) : "l"(a), "l"(b), "l"(c));
    return d;
}
__device__ __forceinline__ void unpack2(unsigned long long v, float& lo, float& hi) {
    asm("mov.b64 {%0, %1}, %2;" : "=f"(lo), "=f"(hi) : "l"(v));
}

// ---------- mma.sync + cp.async helpers (sm_80-compatible PTX) ----------
__device__ __forceinline__ void mma16816(float (&c)[4],
                                         uint32_t a0, uint32_t a1, uint32_t a2, uint32_t a3,
                                         uint32_t b0, uint32_t b1) {
    asm volatile(
        "mma.sync.aligned.m16n8k16.row.col.f32.bf16.bf16.f32 "
        "{%0,%1,%2,%3}, {%4,%5,%6,%7}, {%8,%9}, {%0,%1,%2,%3};"
        : "+f"(c[0]), "+f"(c[1]), "+f"(c[2]), "+f"(c[3])
        : "r"(a0), "r"(a1), "r"(a2), "r"(a3), "r"(b0), "r"(b1));
}
__device__ __forceinline__ void cp16(uint32_t saddr, const void* gptr) {
    asm volatile("cp.async.cg.shared.global [%0], [%1], 16;"
                 :: "r"(saddr), "l"(gptr));
}
#define CP_COMMIT() asm volatile("cp.async.commit_group;" ::: "memory")
#define CP_WAIT1()  asm volatile("cp.async.wait_group 1;" ::: "memory")

// bf16 hi/lo split of an fp32 pair -> two packed bf16x2 words
__device__ __forceinline__ void split2(float v0, float v1, uint32_t& h, uint32_t& l) {
    __nv_bfloat162 hh = __floats2bfloat162_rn(v0, v1);
    h = *(uint32_t*)&hh;
    float r0 = v0 - __bfloat162float(hh.x);
    float r1 = v1 - __bfloat162float(hh.y);
    __nv_bfloat162 ll = __floats2bfloat162_rn(r0, r1);
    l = *(uint32_t*)&ll;
}

// ---------------- attn kernel smem layout (fp32-word offsets) ----------------
#define ATTN_GRID     148
#define TOTAL_WARPS   (ATTN_GRID * 8)
#define BF_U4_STRIDE  36                         // uint4 per d-row (bank-even)
#define BF_BYTES      (128 * BF_U4_STRIDE * 16)  // 73728
#define SL_WORDS      1744                       // per warp-slice
#define SL_NBR_STRIDE 132
#define SL_EXTRA      1584
#define SL_W          1712
#define SL_LG         1728
#define SMEM1_BYTES   (BF_BYTES + 16 * SL_WORDS * 4 + 2 * 128 * 4)   // 186368

__device__ __forceinline__ void issue_bn(uint32_t sa, const float* nbrv,
                                         const float* nbrw, const float* extra,
                                         int bn, int lane) {
    const char* nb = (const char*)(nbrv + (size_t)bn * (Kc * DIMc));
#pragma unroll
    for (int r = 0; r < 12; r++)
        cp16(sa + (uint32_t)(r * SL_NBR_STRIDE + lane * 4) * 4, nb + r * 512 + lane * 16);
    cp16(sa + (uint32_t)(SL_EXTRA + lane * 4) * 4,
         (const char*)(extra + (size_t)bn * DIMc) + lane * 16);
    if (lane < 3)
        cp16(sa + (uint32_t)(SL_W + lane * 4) * 4,
             (const char*)(nbrw + (size_t)bn * Kc) + lane * 16);
}

// =====================================================================
// Kernel 1: bf16-split mma.sync attention + softmax + aggregation.
//   148 CTAs x 256 threads; warp-per-bn, warps fully independent.
//   D[k,d] = en[k,:128] @ W1[:128,:] via 3 bf16 HMMA terms
//   (hi*hi + hi*lo + lo*hi). Epilogue adds wk*W1[128,d], lrelu,
//   dot w2 (quad shfl), 12-wide softmax, fp32 aggregation.
//   B (W1 split) prebuilt in fragment order: one LDS.128 per mma-triple.
// =====================================================================
__global__ __launch_bounds__(256, 1)
void attn_kernel(const float* __restrict__ nbrv,   // [B,N,K,DIM]
                 const float* __restrict__ nbrw,   // [B,N,K]
                 const float* __restrict__ extra,  // [B,N,DIM]
                 const float* __restrict__ w1,     // [129,128]
                 const float* __restrict__ w2p)    // [128,1]
{
    extern __shared__ __align__(16) float smem[];
    uint4* BF      = (uint4*)smem;                     // [128][36] uint4
    float* slices  = smem + BF_BYTES / 4;              // 16 warp-slices
    float* w2_s    = slices + 16 * SL_WORDS;
    float* w1r_s   = w2_s + 128;

    const int t = threadIdx.x, warp = t >> 5, lane = t & 31;
    const int g = lane >> 2, tc = lane & 3;

    // ---- one-time: build W1 fragment table (hi/lo split) ----
#pragma unroll
    for (int i = 0; i < 16; i++) {
        int idx = t + i * 256;                 // 4096 entries = d*32 + ks*4 + tc
        int d = idx >> 5, rem = idx & 31, ks = rem >> 2, tcc = rem & 3;
        int j0 = 16 * ks + 2 * tcc;
        float x0 = w1[j0 * 128 + d],       x1 = w1[(j0 + 1) * 128 + d];
        float y0 = w1[(j0 + 8) * 128 + d], y1 = w1[(j0 + 9) * 128 + d];
        uint32_t b0h, b0l, b1h, b1l;
        split2(x0, x1, b0h, b0l);
        split2(y0, y1, b1h, b1l);
        BF[d * BF_U4_STRIDE + ks * 4 + tcc] = make_uint4(b0h, b1h, b0l, b1l);
    }
    if (t < 128) { w2_s[t] = w2p[t]; w1r_s[t] = w1[128 * 128 + t]; }
    __syncthreads();

    float* sl0 = slices + (warp * 2 + 0) * SL_WORDS;
    float* sl1 = slices + (warp * 2 + 1) * SL_WORDS;
    const uint32_t sa0 = (uint32_t)__cvta_generic_to_shared(sl0);
    const uint32_t sa1 = (uint32_t)__cvta_generic_to_shared(sl1);

    const int gw = blockIdx.x * 8 + warp;

    // prologue: prefetch first bn
    if (gw < BN_TOTAL) issue_bn(sa0, nbrv, nbrw, extra, gw, lane);
    CP_COMMIT();

    int buf = 0;
    for (int bn = gw; bn < BN_TOTAL; bn += TOTAL_WARPS) {
        // prefetch next bn into the other buffer
        int bnN = bn + TOTAL_WARPS;
        if (bnN < BN_TOTAL)
            issue_bn(buf ? sa0 : sa1, nbrv, nbrw, extra, bnN, lane);
        CP_COMMIT();
        CP_WAIT1();            // current bn's data resident
        __syncwarp();

        float* sl = buf ? sl1 : sl0;
        const float* nb = sl;
        const float* ex = sl + SL_EXTRA;

        float acc[16][4];
#pragma unroll
        for (int nt = 0; nt < 16; nt++) {
            acc[nt][0] = 0.f; acc[nt][1] = 0.f; acc[nt][2] = 0.f; acc[nt][3] = 0.f;
        }

        const bool hasHi = (g < 4);            // rows g+8 valid only if < 12
#pragma unroll
        for (int ks = 0; ks < 8; ks++) {
            const int jb = 16 * ks + 2 * tc;
            float2 e0 = *(const float2*)(ex + jb);
            float2 e1 = *(const float2*)(ex + jb + 8);
            float2 p00 = *(const float2*)(nb + g * SL_NBR_STRIDE + jb);
            float2 p01 = *(const float2*)(nb + g * SL_NBR_STRIDE + jb + 8);
            float2 p10 = make_float2(0.f, 0.f), p11 = make_float2(0.f, 0.f);
            if (hasHi) {
                p10 = *(const float2*)(nb + (g + 8) * SL_NBR_STRIDE + jb);
                p11 = *(const float2*)(nb + (g + 8) * SL_NBR_STRIDE + jb + 8);
            }
            uint32_t a0h, a0l, a1h, a1l, a2h, a2l, a3h, a3l;
            split2(e0.x * p00.x, e0.y * p00.y, a0h, a0l);
            split2(e0.x * p10.x, e0.y * p10.y, a1h, a1l);
            split2(e1.x * p01.x, e1.y * p01.y, a2h, a2l);
            split2(e1.x * p11.x, e1.y * p11.y, a3h, a3l);

            const uint4* brow = BF + ks * 4 + tc;
#pragma unroll
            for (int nt = 0; nt < 16; nt++) {
                uint4 b = brow[(nt * 8 + g) * BF_U4_STRIDE];
                mma16816(acc[nt], a0h, a1h, a2h, a3h, b.x, b.y);   // hi*hi
                mma16816(acc[nt], a0h, a1h, a2h, a3h, b.z, b.w);   // hi*lo
                mma16816(acc[nt], a0l, a1l, a2l, a3l, b.x, b.y);   // lo*hi
            }
        }

        // ---- epilogue: logits ----
        const float wg  = sl[SL_W + g];
        const float wg8 = sl[SL_W + g + 8];   // garbage for g>=4 -> rows discarded
        float pg = 0.f, pg8 = 0.f;
#pragma unroll
        for (int nt = 0; nt < 16; nt++) {
            int d0 = nt * 8 + 2 * tc;
            float2 w2v = *(const float2*)(w2_s + d0);
            float2 wrv = *(const float2*)(w1r_s + d0);
            float x;
            x = acc[nt][0] + wg  * wrv.x; pg  += w2v.x * ((x > 0.f) ? x : 0.2f * x);
            x = acc[nt][1] + wg  * wrv.y; pg  += w2v.y * ((x > 0.f) ? x : 0.2f * x);
            x = acc[nt][2] + wg8 * wrv.x; pg8 += w2v.x * ((x > 0.f) ? x : 0.2f * x);
            x = acc[nt][3] + wg8 * wrv.y; pg8 += w2v.y * ((x > 0.f) ? x : 0.2f * x);
        }
        pg  += __shfl_xor_sync(0xffffffffu, pg, 1);
        pg  += __shfl_xor_sync(0xffffffffu, pg, 2);
        pg8 += __shfl_xor_sync(0xffffffffu, pg8, 1);
        pg8 += __shfl_xor_sync(0xffffffffu, pg8, 2);
        if (tc == 0) { sl[SL_LG + g] = pg; sl[SL_LG + g + 8] = pg8; }
        __syncwarp();

        // ---- softmax over k=0..11 (all lanes redundantly) ----
        float lg[12];
        float m = -1e30f;
#pragma unroll
        for (int k = 0; k < 12; k++) { lg[k] = sl[SL_LG + k]; m = fmaxf(m, lg[k]); }
        float ssum = 0.f;
#pragma unroll
        for (int k = 0; k < 12; k++) { lg[k] = __expf(lg[k] - m); ssum += lg[k]; }
        const float inv = 1.0f / ssum;

        // ---- aggregation: lane covers d = lane*4..+3 ----
        float4 a4 = make_float4(0.f, 0.f, 0.f, 0.f);
#pragma unroll
        for (int k = 0; k < 12; k++) {
            float al = lg[k] * inv;
            float4 nv = *(const float4*)(nb + k * SL_NBR_STRIDE + lane * 4);
            a4.x = fmaf(al, nv.x, a4.x);
            a4.y = fmaf(al, nv.y, a4.y);
            a4.z = fmaf(al, nv.z, a4.z);
            a4.w = fmaf(al, nv.w, a4.w);
        }
        *(float4*)(g_agg + (size_t)bn * DIMc + lane * 4) = a4;

        buf ^= 1;
        __syncwarp();          // all lanes done with this buffer before reuse
    }
}

// =====================================================================
// Kernel 2: out = relu(concat(self, agg) @ W3)  (unchanged from R2, 154us)
// =====================================================================
#define OUT_ROWS 16
__global__ __launch_bounds__(512, 1)
void out_kernel(const float* __restrict__ selfv,
                const float* __restrict__ w3,
                float* __restrict__ out)
{
    extern __shared__ __align__(16) float sm[];
    float* xs = sm;
    float* ps = sm + OUT_ROWS * 256;

    const int t = threadIdx.x;
    const int c = t & 127;
    const int h = t >> 7;

    unsigned long long w3r[32];
#pragma unroll
    for (int q = 0; q < 32; q++) {
        int f = h * 64 + 2 * q;
        w3r[q] = pack2(w3[f * 128 + c], w3[(f + 1) * 128 + c]);
    }

    const int warp = t >> 5, lane = t & 31;
    const int n_epochs = BN_TOTAL / OUT_ROWS;

    for (int e = blockIdx.x; e < n_epochs; e += gridDim.x) {
        const int row0 = e * OUT_ROWS;
        __syncthreads();
#pragma unroll
        for (int v = 0; v < 2; v++) {
            int idx = t + v * 512;
            int row = idx >> 6;
            int f4  = idx & 63;
            const float* src = (f4 < 32)
                ? (selfv + (size_t)(row0 + row) * 128 + f4 * 4)
                : (g_agg + (size_t)(row0 + row) * 128 + (f4 - 32) * 4);
            reinterpret_cast<float4*>(xs)[idx] = *reinterpret_cast<const float4*>(src);
        }
        __syncthreads();

#pragma unroll
        for (int row = 0; row < OUT_ROWS; row++) {
            const ulonglong2* xr =
                reinterpret_cast<const ulonglong2*>(xs + row * 256 + h * 64);
            unsigned long long acc0 = 0ull, acc1 = 0ull;
#pragma unroll
            for (int q = 0; q < 16; q++) {
                ulonglong2 xv = xr[q];
                acc0 = fma2(xv.x, w3r[2 * q],     acc0);
                acc1 = fma2(xv.y, w3r[2 * q + 1], acc1);
            }
            float a0, a1, b0, b1;
            unpack2(acc0, a0, a1);
            unpack2(acc1, b0, b1);
            ps[(row * 128 + c) * 5 + h] = (a0 + a1) + (b0 + b1);
        }
        __syncthreads();

        {
            const int row = warp;
            float* pr = ps + row * 128 * 5;
#pragma unroll
            for (int iq = 0; iq < 4; iq++) {
                int cc = lane + 32 * iq;
                float s = pr[cc * 5 + 0] + pr[cc * 5 + 1]
                        + pr[cc * 5 + 2] + pr[cc * 5 + 3];
                out[(size_t)(row0 + row) * 128 + cc] = fmaxf(s, 0.f);
            }
        }
    }
}

// =====================================================================
// Launch.  Inputs: 0 self, 1 neighbor_vector, 2 neighbor_weight,
//   3 extra_vector, 4 masks, 5 batch_size, 6 w_1, 7 w_2, 8 w_3
// =====================================================================
extern "C" void kernel_launch(void* const* d_in, const int* in_sizes, int n_in,
                              void* d_out, int out_size)
{
    const float* selfv = (const float*)d_in[0];
    const float* nbrv  = (const float*)d_in[1];
    const float* nbrw  = (const float*)d_in[2];
    const float* extra = (const float*)d_in[3];
    const float* w1    = (const float*)d_in[6];
    const float* w2    = (const float*)d_in[7];
    const float* w3    = (const float*)d_in[8];
    float* out = (float*)d_out;

    cudaFuncSetAttribute(attn_kernel, cudaFuncAttributeMaxDynamicSharedMemorySize,
                         SMEM1_BYTES);
    attn_kernel<<<ATTN_GRID, 256, SMEM1_BYTES>>>(nbrv, nbrw, extra, w1, w2);

    const int smem2 = (OUT_ROWS * 256 + OUT_ROWS * 128 * 5) * (int)sizeof(float);
    cudaFuncSetAttribute(out_kernel, cudaFuncAttributeMaxDynamicSharedMemorySize, smem2);
    out_kernel<<<148, 512, smem2>>>(selfv, w3, out);
}

// round 9
// speedup vs baseline: 4.5672x; 1.4800x over previous
#include <cuda_runtime.h>
#include <cuda_fp16.h>
#include <cstdint>

// Problem constants (fixed shapes)
#define Bc    128
#define Nc    512
#define Kc    12
#define DIMc  128
#define BN_TOTAL (Bc * Nc)

// Scratch for aggregated neighbor features [B*N, DIM]
__device__ __align__(16) float g_agg[(size_t)BN_TOTAL * DIMc];

// ---------- mma.sync + cp.async helpers (sm_80-compatible PTX) ----------
__device__ __forceinline__ void mma16816(float (&c)[4],
                                         uint32_t a0, uint32_t a1, uint32_t a2, uint32_t a3,
                                         uint32_t b0, uint32_t b1) {
    asm volatile(
        "mma.sync.aligned.m16n8k16.row.col.f32.f16.f16.f32 "
        "{%0,%1,%2,%3}, {%4,%5,%6,%7}, {%8,%9}, {%0,%1,%2,%3};"
        : "+f"(c[0]), "+f"(c[1]), "+f"(c[2]), "+f"(c[3])
        : "r"(a0), "r"(a1), "r"(a2), "r"(a3), "r"(b0), "r"(b1));
}
__device__ __forceinline__ void cp16(uint32_t saddr, const void* gptr) {
    asm volatile("cp.async.cg.shared.global [%0], [%1], 16;"
                 :: "r"(saddr), "l"(gptr));
}
#define CP_COMMIT() asm volatile("cp.async.commit_group;" ::: "memory")
#define CP_WAIT1()  asm volatile("cp.async.wait_group 1;" ::: "memory")

// fp16 hi/lo split of an fp32 pair -> two packed half2 words
__device__ __forceinline__ void split2h(float v0, float v1, uint32_t& h, uint32_t& l) {
    __half2 hh = __floats2half2_rn(v0, v1);
    h = *(uint32_t*)&hh;
    float r0 = v0 - __low2float(hh);
    float r1 = v1 - __high2float(hh);
    __half2 ll = __floats2half2_rn(r0, r1);
    l = *(uint32_t*)&ll;
}
__device__ __forceinline__ uint32_t packh(float v0, float v1) {
    __half2 hh = __floats2half2_rn(v0, v1);
    return *(uint32_t*)&hh;
}

// ---------------- attn kernel smem layout (fp32-word offsets) ----------------
#define ATTN_GRID     148
#define TOTAL_WARPS   (ATTN_GRID * 8)
#define BF_U4_STRIDE  36                         // uint4 per d-row (bank-optimal)
#define BF_BYTES      (128 * BF_U4_STRIDE * 16)  // 73728
#define SL_WORDS      1744                       // per warp-slice (fp32 words)
#define SL_NBR_STRIDE 132
#define SL_EXTRA      1584
#define SL_W          1712
#define SL_LG         1728
#define SMEM1_BYTES   (BF_BYTES + 16 * SL_WORDS * 4 + 2 * 128 * 4)   // 186368

__device__ __forceinline__ void issue_bn(uint32_t sa, const float* nbrv,
                                         const float* nbrw, const float* extra,
                                         int bn, int lane) {
    const char* nb = (const char*)(nbrv + (size_t)bn * (Kc * DIMc));
#pragma unroll
    for (int r = 0; r < 12; r++)
        cp16(sa + (uint32_t)(r * SL_NBR_STRIDE + lane * 4) * 4, nb + r * 512 + lane * 16);
    cp16(sa + (uint32_t)(SL_EXTRA + lane * 4) * 4,
         (const char*)(extra + (size_t)bn * DIMc) + lane * 16);
    if (lane < 3)
        cp16(sa + (uint32_t)(SL_W + lane * 4) * 4,
             (const char*)(nbrw + (size_t)bn * Kc) + lane * 16);
}

// =====================================================================
// Kernel 1: fp16 2-term mma.sync attention + softmax + aggregation.
//   148 CTAs x 256 threads; warp-per-bn, warps fully independent.
//   D[k,d] = en[k,:128] @ W1[:128,:]: A = fp16(en) single operand,
//   B = W1 split hi/lo (error = en_lo*W1 ~ 2^-11, well under 1e-3).
//   Epilogue adds wk*W1[128,d], lrelu, dot w2 (quad shfl), softmax,
//   fp32 aggregation (nbr kept fp32 in slice).
// =====================================================================
__global__ __launch_bounds__(256, 1)
void attn_kernel(const float* __restrict__ nbrv,   // [B,N,K,DIM]
                 const float* __restrict__ nbrw,   // [B,N,K]
                 const float* __restrict__ extra,  // [B,N,DIM]
                 const float* __restrict__ w1,     // [129,128]
                 const float* __restrict__ w2p)    // [128,1]
{
    extern __shared__ __align__(16) float smem[];
    uint4* BF      = (uint4*)smem;                     // [128][36] uint4
    float* slices  = smem + BF_BYTES / 4;              // 16 warp-slices
    float* w2_s    = slices + 16 * SL_WORDS;
    float* w1r_s   = w2_s + 128;

    const int t = threadIdx.x, warp = t >> 5, lane = t & 31;
    const int g = lane >> 2, tc = lane & 3;

    // ---- one-time: build W1 fragment table (fp16 hi/lo split) ----
#pragma unroll
    for (int i = 0; i < 16; i++) {
        int idx = t + i * 256;                 // 4096 entries = d*32 + ks*4 + tc
        int d = idx >> 5, rem = idx & 31, ks = rem >> 2, tcc = rem & 3;
        int j0 = 16 * ks + 2 * tcc;
        float x0 = w1[j0 * 128 + d],       x1 = w1[(j0 + 1) * 128 + d];
        float y0 = w1[(j0 + 8) * 128 + d], y1 = w1[(j0 + 9) * 128 + d];
        uint32_t b0h, b0l, b1h, b1l;
        split2h(x0, x1, b0h, b0l);
        split2h(y0, y1, b1h, b1l);
        BF[d * BF_U4_STRIDE + ks * 4 + tcc] = make_uint4(b0h, b1h, b0l, b1l);
    }
    if (t < 128) { w2_s[t] = w2p[t]; w1r_s[t] = w1[128 * 128 + t]; }
    __syncthreads();

    float* sl0 = slices + (warp * 2 + 0) * SL_WORDS;
    float* sl1 = slices + (warp * 2 + 1) * SL_WORDS;
    const uint32_t sa0 = (uint32_t)__cvta_generic_to_shared(sl0);
    const uint32_t sa1 = (uint32_t)__cvta_generic_to_shared(sl1);

    const int gw = blockIdx.x * 8 + warp;

    if (gw < BN_TOTAL) issue_bn(sa0, nbrv, nbrw, extra, gw, lane);
    CP_COMMIT();

    int buf = 0;
    for (int bn = gw; bn < BN_TOTAL; bn += TOTAL_WARPS) {
        int bnN = bn + TOTAL_WARPS;
        if (bnN < BN_TOTAL)
            issue_bn(buf ? sa0 : sa1, nbrv, nbrw, extra, bnN, lane);
        CP_COMMIT();
        CP_WAIT1();
        __syncwarp();

        float* sl = buf ? sl1 : sl0;
        const float* nb = sl;
        const float* ex = sl + SL_EXTRA;

        float acc[16][4];
#pragma unroll
        for (int nt = 0; nt < 16; nt++) {
            acc[nt][0] = 0.f; acc[nt][1] = 0.f; acc[nt][2] = 0.f; acc[nt][3] = 0.f;
        }

        const bool hasHi = (g < 4);            // rows g+8 valid only if < 12
#pragma unroll
        for (int ks = 0; ks < 8; ks++) {
            const int jb = 16 * ks + 2 * tc;
            float2 e0 = *(const float2*)(ex + jb);
            float2 e1 = *(const float2*)(ex + jb + 8);
            float2 p00 = *(const float2*)(nb + g * SL_NBR_STRIDE + jb);
            float2 p01 = *(const float2*)(nb + g * SL_NBR_STRIDE + jb + 8);
            float2 p10 = make_float2(0.f, 0.f), p11 = make_float2(0.f, 0.f);
            if (hasHi) {
                p10 = *(const float2*)(nb + (g + 8) * SL_NBR_STRIDE + jb);
                p11 = *(const float2*)(nb + (g + 8) * SL_NBR_STRIDE + jb + 8);
            }
            uint32_t a0 = packh(e0.x * p00.x, e0.y * p00.y);
            uint32_t a1 = packh(e0.x * p10.x, e0.y * p10.y);
            uint32_t a2 = packh(e1.x * p01.x, e1.y * p01.y);
            uint32_t a3 = packh(e1.x * p11.x, e1.y * p11.y);

            const uint4* brow = BF + ks * 4 + tc;
#pragma unroll
            for (int nt = 0; nt < 16; nt++) {
                uint4 b = brow[(nt * 8 + g) * BF_U4_STRIDE];
                mma16816(acc[nt], a0, a1, a2, a3, b.x, b.y);   // A * Bhi
                mma16816(acc[nt], a0, a1, a2, a3, b.z, b.w);   // A * Blo
            }
        }

        // ---- epilogue: logits ----
        const float wg  = sl[SL_W + g];
        const float wg8 = sl[SL_W + g + 8];   // garbage for g>=4 -> rows discarded
        float pg = 0.f, pg8 = 0.f;
#pragma unroll
        for (int nt = 0; nt < 16; nt++) {
            int d0 = nt * 8 + 2 * tc;
            float2 w2v = *(const float2*)(w2_s + d0);
            float2 wrv = *(const float2*)(w1r_s + d0);
            float x;
            x = acc[nt][0] + wg  * wrv.x; pg  += w2v.x * ((x > 0.f) ? x : 0.2f * x);
            x = acc[nt][1] + wg  * wrv.y; pg  += w2v.y * ((x > 0.f) ? x : 0.2f * x);
            x = acc[nt][2] + wg8 * wrv.x; pg8 += w2v.x * ((x > 0.f) ? x : 0.2f * x);
            x = acc[nt][3] + wg8 * wrv.y; pg8 += w2v.y * ((x > 0.f) ? x : 0.2f * x);
        }
        pg  += __shfl_xor_sync(0xffffffffu, pg, 1);
        pg  += __shfl_xor_sync(0xffffffffu, pg, 2);
        pg8 += __shfl_xor_sync(0xffffffffu, pg8, 1);
        pg8 += __shfl_xor_sync(0xffffffffu, pg8, 2);
        if (tc == 0) { sl[SL_LG + g] = pg; sl[SL_LG + g + 8] = pg8; }
        __syncwarp();

        // ---- softmax over k=0..11 (all lanes redundantly) ----
        float lg[12];
        float m = -1e30f;
#pragma unroll
        for (int k = 0; k < 12; k++) { lg[k] = sl[SL_LG + k]; m = fmaxf(m, lg[k]); }
        float ssum = 0.f;
#pragma unroll
        for (int k = 0; k < 12; k++) { lg[k] = __expf(lg[k] - m); ssum += lg[k]; }
        const float inv = 1.0f / ssum;

        // ---- aggregation: lane covers d = lane*4..+3 (fp32 exact) ----
        float4 a4 = make_float4(0.f, 0.f, 0.f, 0.f);
#pragma unroll
        for (int k = 0; k < 12; k++) {
            float al = lg[k] * inv;
            float4 nv = *(const float4*)(nb + k * SL_NBR_STRIDE + lane * 4);
            a4.x = fmaf(al, nv.x, a4.x);
            a4.y = fmaf(al, nv.y, a4.y);
            a4.z = fmaf(al, nv.z, a4.z);
            a4.w = fmaf(al, nv.w, a4.w);
        }
        *(float4*)(g_agg + (size_t)bn * DIMc + lane * 4) = a4;

        buf ^= 1;
        __syncwarp();
    }
}

// =====================================================================
// Kernel 2: out = relu(concat(self, agg) @ W3) via fp16 2-term mma.
//   148 CTAs x 256 threads (8 warps). W3 hi/lo fragment table in smem
//   (stride 66 uint4 -> optimal 4-phase LDS.128). Per pass: CTA covers
//   128 rows; warp stages its 16 rows as fp16 half2 words (stride 132
//   -> conflict-free LDS.32 A-frags), then 16ks x 16nt x 2 mma.
// =====================================================================
#define BF3_U4_STRIDE 66
#define BF3_BYTES     (128 * BF3_U4_STRIDE * 16)     // 135168
#define XH_STRIDE     132                            // u32 words per row
#define XH_WORDS      (16 * XH_STRIDE)               // per warp
#define SMEM2_BYTES   (((BF3_BYTES + 8 * XH_WORDS * 4) + 1023) & ~1023)  // 202752->203776

__global__ __launch_bounds__(256, 1)
void out_kernel(const float* __restrict__ selfv,  // [B,N,DIM]
                const float* __restrict__ w3,     // [256,128]
                float* __restrict__ out)          // [B,N,DIM]
{
    extern __shared__ __align__(16) float smem[];
    uint4*    BF3 = (uint4*)smem;
    uint32_t* xh  = (uint32_t*)(smem + BF3_BYTES / 4);

    const int t = threadIdx.x, warp = t >> 5, lane = t & 31;
    const int g = lane >> 2, tc = lane & 3;

    // ---- one-time: W3 fragment table (fp16 hi/lo) ----
#pragma unroll
    for (int i = 0; i < 32; i++) {
        int idx = t + i * 256;                 // 8192 entries = d*64 + ks*4 + tc
        int d = idx >> 6, rem = idx & 63, ks = rem >> 2, tcc = rem & 3;
        int j0 = 16 * ks + 2 * tcc;
        float x0 = w3[j0 * 128 + d],       x1 = w3[(j0 + 1) * 128 + d];
        float y0 = w3[(j0 + 8) * 128 + d], y1 = w3[(j0 + 9) * 128 + d];
        uint32_t b0h, b0l, b1h, b1l;
        split2h(x0, x1, b0h, b0l);
        split2h(y0, y1, b1h, b1l);
        BF3[d * BF3_U4_STRIDE + ks * 4 + tcc] = make_uint4(b0h, b1h, b0l, b1l);
    }
    __syncthreads();

    uint32_t* xw = xh + warp * XH_WORDS;
    const int n_pass = BN_TOTAL / 128;        // 512

    for (int p = blockIdx.x; p < n_pass; p += gridDim.x) {
        const int row0 = p * 128 + warp * 16;  // this warp's 16 rows

        // ---- stage x = concat(self, agg) as fp16 half2 words ----
        // 16 rows x 64 float4 = 1024 float4; lane handles 32 (coalesced)
#pragma unroll
        for (int i = 0; i < 32; i++) {
            int idx = i * 32 + lane;
            int row = idx >> 6, f4 = idx & 63;
            const float4 v = (f4 < 32)
                ? *(const float4*)(selfv + (size_t)(row0 + row) * 128 + f4 * 4)
                : *(const float4*)(g_agg + (size_t)(row0 + row) * 128 + (f4 - 32) * 4);
            uint2 w2v;
            w2v.x = packh(v.x, v.y);
            w2v.y = packh(v.z, v.w);
            *(uint2*)(xw + row * XH_STRIDE + f4 * 2) = w2v;
        }
        __syncwarp();

        float acc[16][4];
#pragma unroll
        for (int nt = 0; nt < 16; nt++) {
            acc[nt][0] = 0.f; acc[nt][1] = 0.f; acc[nt][2] = 0.f; acc[nt][3] = 0.f;
        }

#pragma unroll
        for (int ks = 0; ks < 16; ks++) {
            // A frag: x[row g / g+8][j = 16ks+2tc (+8)]
            uint32_t a0 = xw[g * XH_STRIDE + 8 * ks + tc];
            uint32_t a1 = xw[(g + 8) * XH_STRIDE + 8 * ks + tc];
            uint32_t a2 = xw[g * XH_STRIDE + 8 * ks + tc + 4];
            uint32_t a3 = xw[(g + 8) * XH_STRIDE + 8 * ks + tc + 4];
            const uint4* brow = BF3 + ks * 4 + tc;
#pragma unroll
            for (int nt = 0; nt < 16; nt++) {
                uint4 b = brow[(nt * 8 + g) * BF3_U4_STRIDE];
                mma16816(acc[nt], a0, a1, a2, a3, b.x, b.y);
                mma16816(acc[nt], a0, a1, a2, a3, b.z, b.w);
            }
        }

        // ---- epilogue: relu + store ----
#pragma unroll
        for (int nt = 0; nt < 16; nt++) {
            int d0 = nt * 8 + 2 * tc;
            float2 v0 = make_float2(fmaxf(acc[nt][0], 0.f), fmaxf(acc[nt][1], 0.f));
            float2 v1 = make_float2(fmaxf(acc[nt][2], 0.f), fmaxf(acc[nt][3], 0.f));
            *(float2*)(out + (size_t)(row0 + g) * 128 + d0)     = v0;
            *(float2*)(out + (size_t)(row0 + g + 8) * 128 + d0) = v1;
        }
        __syncwarp();   // xw reuse next pass
    }
}

// =====================================================================
// Launch.  Inputs: 0 self, 1 neighbor_vector, 2 neighbor_weight,
//   3 extra_vector, 4 masks, 5 batch_size, 6 w_1, 7 w_2, 8 w_3
// =====================================================================
extern "C" void kernel_launch(void* const* d_in, const int* in_sizes, int n_in,
                              void* d_out, int out_size)
{
    const float* selfv = (const float*)d_in[0];
    const float* nbrv  = (const float*)d_in[1];
    const float* nbrw  = (const float*)d_in[2];
    const float* extra = (const float*)d_in[3];
    const float* w1    = (const float*)d_in[6];
    const float* w2    = (const float*)d_in[7];
    const float* w3    = (const float*)d_in[8];
    float* out = (float*)d_out;

    cudaFuncSetAttribute(attn_kernel, cudaFuncAttributeMaxDynamicSharedMemorySize,
                         SMEM1_BYTES);
    attn_kernel<<<ATTN_GRID, 256, SMEM1_BYTES>>>(nbrv, nbrw, extra, w1, w2);

    cudaFuncSetAttribute(out_kernel, cudaFuncAttributeMaxDynamicSharedMemorySize,
                         SMEM2_BYTES);
    out_kernel<<<148, 256, SMEM2_BYTES>>>(selfv, w3, out);
}

// round 10
// speedup vs baseline: 6.1569x; 1.3481x over previous
#include <cuda_runtime.h>
#include <cuda_fp16.h>
#include <cstdint>

// Problem constants (fixed shapes)
#define Bc    128
#define Nc    512
#define Kc    12
#define DIMc  128
#define BN_TOTAL (Bc * Nc)

// Scratch for aggregated neighbor features [B*N, DIM]
__device__ __align__(16) float g_agg[(size_t)BN_TOTAL * DIMc];

// ---------- mma.sync + cp.async helpers (sm_80-compatible PTX) ----------
__device__ __forceinline__ void mma16816(float (&c)[4],
                                         uint32_t a0, uint32_t a1, uint32_t a2, uint32_t a3,
                                         uint32_t b0, uint32_t b1) {
    asm volatile(
        "mma.sync.aligned.m16n8k16.row.col.f32.f16.f16.f32 "
        "{%0,%1,%2,%3}, {%4,%5,%6,%7}, {%8,%9}, {%0,%1,%2,%3};"
        : "+f"(c[0]), "+f"(c[1]), "+f"(c[2]), "+f"(c[3])
        : "r"(a0), "r"(a1), "r"(a2), "r"(a3), "r"(b0), "r"(b1));
}
__device__ __forceinline__ void cp16(uint32_t saddr, const void* gptr) {
    asm volatile("cp.async.cg.shared.global [%0], [%1], 16;"
                 :: "r"(saddr), "l"(gptr));
}
#define CP_COMMIT() asm volatile("cp.async.commit_group;" ::: "memory")
#define CP_WAIT1()  asm volatile("cp.async.wait_group 1;" ::: "memory")

__device__ __forceinline__ uint32_t packh(float v0, float v1) {
    __half2 hh = __floats2half2_rn(v0, v1);
    return *(uint32_t*)&hh;
}

// ---------------- attn kernel smem layout ----------------
#define ATTN_GRID     148
#define TOTAL_WARPS   (ATTN_GRID * 8)
#define BF_U4_STRIDE  20                         // uint4 per d-row (conflict-free)
#define BF_BYTES      (128 * BF_U4_STRIDE * 16)  // 40960
#define SL_WORDS      1744                       // per warp-slice (fp32 words)
#define SL_NBR_STRIDE 132
#define SL_EXTRA      1584
#define SL_W          1712
#define SL_LG         1728
#define SMEM1_BYTES   (BF_BYTES + 16 * SL_WORDS * 4 + 2 * 128 * 4)   // 153600

__device__ __forceinline__ void issue_bn(uint32_t sa, const float* nbrv,
                                         const float* nbrw, const float* extra,
                                         int bn, int lane) {
    const char* nb = (const char*)(nbrv + (size_t)bn * (Kc * DIMc));
#pragma unroll
    for (int r = 0; r < 12; r++)
        cp16(sa + (uint32_t)(r * SL_NBR_STRIDE + lane * 4) * 4, nb + r * 512 + lane * 16);
    cp16(sa + (uint32_t)(SL_EXTRA + lane * 4) * 4,
         (const char*)(extra + (size_t)bn * DIMc) + lane * 16);
    if (lane < 3)
        cp16(sa + (uint32_t)(SL_W + lane * 4) * 4,
             (const char*)(nbrw + (size_t)bn * Kc) + lane * 16);
}

// =====================================================================
// Kernel 1: fp16 1-term mma.sync attention + softmax + aggregation.
//   148 CTAs x 256 threads; warp-per-bn. D[k,d] = fp16(en) @ fp16(W1).
//   B table packs ks-pairs per uint4: {b0[ks],b1[ks],b0[ks+1],b1[ks+1]}
//   (stride 20 uint4 -> conflict-free LDS.128 feeding 2 mma).
//   Epilogue adds wk*W1[128,d] (fp32), lrelu, dot w2, softmax,
//   fp32 aggregation.
// =====================================================================
__global__ __launch_bounds__(256, 1)
void attn_kernel(const float* __restrict__ nbrv,   // [B,N,K,DIM]
                 const float* __restrict__ nbrw,   // [B,N,K]
                 const float* __restrict__ extra,  // [B,N,DIM]
                 const float* __restrict__ w1,     // [129,128]
                 const float* __restrict__ w2p)    // [128,1]
{
    extern __shared__ __align__(16) float smem[];
    uint4* BF      = (uint4*)smem;                     // [128][20] uint4
    float* slices  = smem + BF_BYTES / 4;              // 16 warp-slices
    float* w2_s    = slices + 16 * SL_WORDS;
    float* w1r_s   = w2_s + 128;

    const int t = threadIdx.x, warp = t >> 5, lane = t & 31;
    const int g = lane >> 2, tc = lane & 3;

    // ---- one-time: W1 fragment table, fp16, ks-pairs packed ----
#pragma unroll
    for (int i = 0; i < 8; i++) {
        int idx = t + i * 256;                 // 2048 entries = d*16 + ks2*4 + tc
        int d = idx >> 4, rem = idx & 15, ks2 = rem >> 2, tcc = rem & 3;
        int jA = 32 * ks2 + 2 * tcc;           // ks = 2*ks2
        int jB = jA + 16;                      // ks = 2*ks2+1
        uint32_t b0A = packh(w1[jA * 128 + d],       w1[(jA + 1) * 128 + d]);
        uint32_t b1A = packh(w1[(jA + 8) * 128 + d], w1[(jA + 9) * 128 + d]);
        uint32_t b0B = packh(w1[jB * 128 + d],       w1[(jB + 1) * 128 + d]);
        uint32_t b1B = packh(w1[(jB + 8) * 128 + d], w1[(jB + 9) * 128 + d]);
        BF[d * BF_U4_STRIDE + ks2 * 4 + tcc] = make_uint4(b0A, b1A, b0B, b1B);
    }
    if (t < 128) { w2_s[t] = w2p[t]; w1r_s[t] = w1[128 * 128 + t]; }
    __syncthreads();

    float* sl0 = slices + (warp * 2 + 0) * SL_WORDS;
    float* sl1 = slices + (warp * 2 + 1) * SL_WORDS;
    const uint32_t sa0 = (uint32_t)__cvta_generic_to_shared(sl0);
    const uint32_t sa1 = (uint32_t)__cvta_generic_to_shared(sl1);

    const int gw = blockIdx.x * 8 + warp;

    if (gw < BN_TOTAL) issue_bn(sa0, nbrv, nbrw, extra, gw, lane);
    CP_COMMIT();

    int buf = 0;
    for (int bn = gw; bn < BN_TOTAL; bn += TOTAL_WARPS) {
        int bnN = bn + TOTAL_WARPS;
        if (bnN < BN_TOTAL)
            issue_bn(buf ? sa0 : sa1, nbrv, nbrw, extra, bnN, lane);
        CP_COMMIT();
        CP_WAIT1();
        __syncwarp();

        float* sl = buf ? sl1 : sl0;
        const float* nb = sl;
        const float* ex = sl + SL_EXTRA;

        float acc[16][4];
#pragma unroll
        for (int nt = 0; nt < 16; nt++) {
            acc[nt][0] = 0.f; acc[nt][1] = 0.f; acc[nt][2] = 0.f; acc[nt][3] = 0.f;
        }

        const bool hasHi = (g < 4);            // rows g+8 valid only if < 12
#pragma unroll
        for (int ks2 = 0; ks2 < 4; ks2++) {
            uint32_t a[2][4];
#pragma unroll
            for (int s = 0; s < 2; s++) {
                const int jb = 32 * ks2 + 16 * s + 2 * tc;
                float2 e0 = *(const float2*)(ex + jb);
                float2 e1 = *(const float2*)(ex + jb + 8);
                float2 p00 = *(const float2*)(nb + g * SL_NBR_STRIDE + jb);
                float2 p01 = *(const float2*)(nb + g * SL_NBR_STRIDE + jb + 8);
                float2 p10 = make_float2(0.f, 0.f), p11 = make_float2(0.f, 0.f);
                if (hasHi) {
                    p10 = *(const float2*)(nb + (g + 8) * SL_NBR_STRIDE + jb);
                    p11 = *(const float2*)(nb + (g + 8) * SL_NBR_STRIDE + jb + 8);
                }
                a[s][0] = packh(e0.x * p00.x, e0.y * p00.y);
                a[s][1] = packh(e0.x * p10.x, e0.y * p10.y);
                a[s][2] = packh(e1.x * p01.x, e1.y * p01.y);
                a[s][3] = packh(e1.x * p11.x, e1.y * p11.y);
            }
            const uint4* brow = BF + ks2 * 4 + tc;
#pragma unroll
            for (int nt = 0; nt < 16; nt++) {
                uint4 b = brow[(nt * 8 + g) * BF_U4_STRIDE];
                mma16816(acc[nt], a[0][0], a[0][1], a[0][2], a[0][3], b.x, b.y);
                mma16816(acc[nt], a[1][0], a[1][1], a[1][2], a[1][3], b.z, b.w);
            }
        }

        // ---- epilogue: logits ----
        const float wg  = sl[SL_W + g];
        const float wg8 = sl[SL_W + g + 8];   // garbage for g>=4 -> rows discarded
        float pg = 0.f, pg8 = 0.f;
#pragma unroll
        for (int nt = 0; nt < 16; nt++) {
            int d0 = nt * 8 + 2 * tc;
            float2 w2v = *(const float2*)(w2_s + d0);
            float2 wrv = *(const float2*)(w1r_s + d0);
            float x;
            x = acc[nt][0] + wg  * wrv.x; pg  += w2v.x * ((x > 0.f) ? x : 0.2f * x);
            x = acc[nt][1] + wg  * wrv.y; pg  += w2v.y * ((x > 0.f) ? x : 0.2f * x);
            x = acc[nt][2] + wg8 * wrv.x; pg8 += w2v.x * ((x > 0.f) ? x : 0.2f * x);
            x = acc[nt][3] + wg8 * wrv.y; pg8 += w2v.y * ((x > 0.f) ? x : 0.2f * x);
        }
        pg  += __shfl_xor_sync(0xffffffffu, pg, 1);
        pg  += __shfl_xor_sync(0xffffffffu, pg, 2);
        pg8 += __shfl_xor_sync(0xffffffffu, pg8, 1);
        pg8 += __shfl_xor_sync(0xffffffffu, pg8, 2);
        if (tc == 0) { sl[SL_LG + g] = pg; sl[SL_LG + g + 8] = pg8; }
        __syncwarp();

        // ---- softmax over k=0..11 (all lanes redundantly) ----
        float lg[12];
        float m = -1e30f;
#pragma unroll
        for (int k = 0; k < 12; k++) { lg[k] = sl[SL_LG + k]; m = fmaxf(m, lg[k]); }
        float ssum = 0.f;
#pragma unroll
        for (int k = 0; k < 12; k++) { lg[k] = __expf(lg[k] - m); ssum += lg[k]; }
        const float inv = 1.0f / ssum;

        // ---- aggregation: lane covers d = lane*4..+3 (fp32 exact) ----
        float4 a4 = make_float4(0.f, 0.f, 0.f, 0.f);
#pragma unroll
        for (int k = 0; k < 12; k++) {
            float al = lg[k] * inv;
            float4 nv = *(const float4*)(nb + k * SL_NBR_STRIDE + lane * 4);
            a4.x = fmaf(al, nv.x, a4.x);
            a4.y = fmaf(al, nv.y, a4.y);
            a4.z = fmaf(al, nv.z, a4.z);
            a4.w = fmaf(al, nv.w, a4.w);
        }
        *(float4*)(g_agg + (size_t)bn * DIMc + lane * 4) = a4;

        buf ^= 1;
        __syncwarp();
    }
}

// =====================================================================
// Kernel 2: out = relu(concat(self, agg) @ W3) via fp16 1-term mma.
//   148 CTAs x 512 threads (16 warps = 4/SMSP). warp = (rowgroup rg,
//   colhalf ch): 16 rows, 64 cols (8 nt -> 32 acc regs). W3 table packs
//   ks-pairs per uint4 (stride 36, conflict-free). Warp pair (2rg,2rg+1)
//   stages rowgroup rg's x as fp16.
// =====================================================================
#define BF3_U4_STRIDE 36
#define BF3_BYTES     (128 * BF3_U4_STRIDE * 16)     // 73728
#define XH_STRIDE     132                            // u32 words per row
#define XH_WORDS      (16 * XH_STRIDE)               // per rowgroup
#define SMEM2_BYTES   (BF3_BYTES + 8 * XH_WORDS * 4) // 73728+67584=141312

__global__ __launch_bounds__(512, 1)
void out_kernel(const float* __restrict__ selfv,  // [B,N,DIM]
                const float* __restrict__ w3,     // [256,128]
                float* __restrict__ out)          // [B,N,DIM]
{
    extern __shared__ __align__(16) float smem[];
    uint4*    BF3 = (uint4*)smem;
    uint32_t* xh  = (uint32_t*)(smem + BF3_BYTES / 4);

    const int t = threadIdx.x, warp = t >> 5, lane = t & 31;
    const int g = lane >> 2, tc = lane & 3;
    const int rg = warp >> 1, ch = warp & 1;
    const int pairlane = t & 63;

    // ---- one-time: W3 fragment table (fp16, ks-pairs packed) ----
#pragma unroll
    for (int i = 0; i < 8; i++) {
        int idx = t + i * 512;                 // 4096 entries = d*32 + ks2*4 + tc
        int d = idx >> 5, rem = idx & 31, ks2 = rem >> 2, tcc = rem & 3;
        int jA = 32 * ks2 + 2 * tcc;           // ks = 2*ks2
        int jB = jA + 16;                      // ks = 2*ks2+1
        uint32_t b0A = packh(w3[jA * 128 + d],       w3[(jA + 1) * 128 + d]);
        uint32_t b1A = packh(w3[(jA + 8) * 128 + d], w3[(jA + 9) * 128 + d]);
        uint32_t b0B = packh(w3[jB * 128 + d],       w3[(jB + 1) * 128 + d]);
        uint32_t b1B = packh(w3[(jB + 8) * 128 + d], w3[(jB + 9) * 128 + d]);
        BF3[d * BF3_U4_STRIDE + ks2 * 4 + tcc] = make_uint4(b0A, b1A, b0B, b1B);
    }
    __syncthreads();

    uint32_t* xw = xh + rg * XH_WORDS;
    const int n_pass = BN_TOTAL / 128;        // 512

    for (int p = blockIdx.x; p < n_pass; p += gridDim.x) {
        const int row0 = p * 128 + rg * 16;    // this rowgroup's 16 rows

        // ---- stage x = concat(self, agg) as fp16 (warp pair, 64 lanes) ----
        // 16 rows x 64 float4 = 1024 f4; 16 per lane
#pragma unroll
        for (int i = 0; i < 16; i++) {
            int idx = i * 64 + pairlane;
            int row = idx >> 6, f4 = idx & 63;
            const float4 v = (f4 < 32)
                ? *(const float4*)(selfv + (size_t)(row0 + row) * 128 + f4 * 4)
                : *(const float4*)(g_agg + (size_t)(row0 + row) * 128 + (f4 - 32) * 4);
            uint2 w2v;
            w2v.x = packh(v.x, v.y);
            w2v.y = packh(v.z, v.w);
            *(uint2*)(xw + row * XH_STRIDE + f4 * 2) = w2v;
        }
        __syncthreads();

        float acc[8][4];
#pragma unroll
        for (int nt = 0; nt < 8; nt++) {
            acc[nt][0] = 0.f; acc[nt][1] = 0.f; acc[nt][2] = 0.f; acc[nt][3] = 0.f;
        }

#pragma unroll
        for (int ks2 = 0; ks2 < 8; ks2++) {
            uint32_t a[2][4];
#pragma unroll
            for (int s = 0; s < 2; s++) {
                int ks = 2 * ks2 + s;
                a[s][0] = xw[g * XH_STRIDE + 8 * ks + tc];
                a[s][1] = xw[(g + 8) * XH_STRIDE + 8 * ks + tc];
                a[s][2] = xw[g * XH_STRIDE + 8 * ks + tc + 4];
                a[s][3] = xw[(g + 8) * XH_STRIDE + 8 * ks + tc + 4];
            }
            const uint4* brow = BF3 + ks2 * 4 + tc;
#pragma unroll
            for (int nt = 0; nt < 8; nt++) {
                uint4 b = brow[(ch * 64 + nt * 8 + g) * BF3_U4_STRIDE];
                mma16816(acc[nt], a[0][0], a[0][1], a[0][2], a[0][3], b.x, b.y);
                mma16816(acc[nt], a[1][0], a[1][1], a[1][2], a[1][3], b.z, b.w);
            }
        }

        // ---- epilogue: relu + store (warp's 64-col half) ----
#pragma unroll
        for (int nt = 0; nt < 8; nt++) {
            int d0 = ch * 64 + nt * 8 + 2 * tc;
            float2 v0 = make_float2(fmaxf(acc[nt][0], 0.f), fmaxf(acc[nt][1], 0.f));
            float2 v1 = make_float2(fmaxf(acc[nt][2], 0.f), fmaxf(acc[nt][3], 0.f));
            *(float2*)(out + (size_t)(row0 + g) * 128 + d0)     = v0;
            *(float2*)(out + (size_t)(row0 + g + 8) * 128 + d0) = v1;
        }
        __syncthreads();   // xw reuse next pass
    }
}

// =====================================================================
// Launch.  Inputs: 0 self, 1 neighbor_vector, 2 neighbor_weight,
//   3 extra_vector, 4 masks, 5 batch_size, 6 w_1, 7 w_2, 8 w_3
// =====================================================================
extern "C" void kernel_launch(void* const* d_in, const int* in_sizes, int n_in,
                              void* d_out, int out_size)
{
    const float* selfv = (const float*)d_in[0];
    const float* nbrv  = (const float*)d_in[1];
    const float* nbrw  = (const float*)d_in[2];
    const float* extra = (const float*)d_in[3];
    const float* w1    = (const float*)d_in[6];
    const float* w2    = (const float*)d_in[7];
    const float* w3    = (const float*)d_in[8];
    float* out = (float*)d_out;

    cudaFuncSetAttribute(attn_kernel, cudaFuncAttributeMaxDynamicSharedMemorySize,
                         SMEM1_BYTES);
    attn_kernel<<<ATTN_GRID, 256, SMEM1_BYTES>>>(nbrv, nbrw, extra, w1, w2);

    cudaFuncSetAttribute(out_kernel, cudaFuncAttributeMaxDynamicSharedMemorySize,
                         SMEM2_BYTES);
    out_kernel<<<148, 512, SMEM2_BYTES>>>(selfv, w3, out);
}

// round 12
// speedup vs baseline: 6.5555x; 1.0647x over previous
#include <cuda_runtime.h>
#include <cuda_fp16.h>
#include <cstdint>

// Problem constants (fixed shapes)
#define Bc    128
#define Nc    512
#define Kc    12
#define DIMc  128
#define BN_TOTAL (Bc * Nc)

// Scratch for aggregated neighbor features [B*N, DIM]
__device__ __align__(16) float g_agg[(size_t)BN_TOTAL * DIMc];

// ---------- mma.sync + cp.async helpers (sm_80-compatible PTX) ----------
__device__ __forceinline__ void mma16816(float (&c)[4],
                                         uint32_t a0, uint32_t a1, uint32_t a2, uint32_t a3,
                                         uint32_t b0, uint32_t b1) {
    asm volatile(
        "mma.sync.aligned.m16n8k16.row.col.f32.f16.f16.f32 "
        "{%0,%1,%2,%3}, {%4,%5,%6,%7}, {%8,%9}, {%0,%1,%2,%3};"
        : "+f"(c[0]), "+f"(c[1]), "+f"(c[2]), "+f"(c[3])
        : "r"(a0), "r"(a1), "r"(a2), "r"(a3), "r"(b0), "r"(b1));
}
__device__ __forceinline__ void cp16(uint32_t saddr, const void* gptr) {
    asm volatile("cp.async.cg.shared.global [%0], [%1], 16;"
                 :: "r"(saddr), "l"(gptr));
}
#define CP_COMMIT() asm volatile("cp.async.commit_group;" ::: "memory")
#define CP_WAIT0()  asm volatile("cp.async.wait_group 0;" ::: "memory")

__device__ __forceinline__ uint32_t packh(float v0, float v1) {
    __half2 hh = __floats2half2_rn(v0, v1);
    return *(uint32_t*)&hh;
}

// ---------------- attn kernel smem layout ----------------
#define ATTN_GRID     148
#define ATTN_WARPS    16
#define TOTAL_WARPS   (ATTN_GRID * ATTN_WARPS)
#define BF_U4_STRIDE  20                         // uint4 per d-row (conflict-free)
#define BF_BYTES      (128 * BF_U4_STRIDE * 16)  // 40960
#define SL_WORDS      1744                       // per warp-slice (fp32 words)
#define SL_NBR_STRIDE 132
#define SL_EXTRA      1584
#define SL_W          1712
#define SL_LG         1728
#define SMEM1_USED    (BF_BYTES + ATTN_WARPS * SL_WORDS * 4 + 2 * 128 * 4)  // 153600
#define SMEM1_BYTES   ((SMEM1_USED + 1023) & ~1023)                          // 153600

__device__ __forceinline__ void issue_bn(uint32_t sa, const float* nbrv,
                                         const float* nbrw, const float* extra,
                                         int bn, int lane) {
    const char* nb = (const char*)(nbrv + (size_t)bn * (Kc * DIMc));
#pragma unroll
    for (int r = 0; r < 12; r++)
        cp16(sa + (uint32_t)(r * SL_NBR_STRIDE + lane * 4) * 4, nb + r * 512 + lane * 16);
    cp16(sa + (uint32_t)(SL_EXTRA + lane * 4) * 4,
         (const char*)(extra + (size_t)bn * DIMc) + lane * 16);
    if (lane < 3)
        cp16(sa + (uint32_t)(SL_W + lane * 4) * 4,
             (const char*)(nbrw + (size_t)bn * Kc) + lane * 16);
}

// =====================================================================
// Kernel 1: fp16 1-term mma.sync attention + softmax + aggregation.
//   148 CTAs x 512 threads (16 warps = 4/SMSP); warp-per-bn, single
//   cp.async buffer per warp (cross-warp latency hiding).
//   D[k,d] = fp16(en) @ fp16(W1); B table packs ks-pairs per uint4
//   (stride 20 -> conflict-free LDS.128 feeding 2 mma). Epilogue adds
//   wk*W1[128,d] (fp32), lrelu, dot w2, softmax, fp32 aggregation.
// =====================================================================
__global__ __launch_bounds__(512, 1)
void attn_kernel(const float* __restrict__ nbrv,   // [B,N,K,DIM]
                 const float* __restrict__ nbrw,   // [B,N,K]
                 const float* __restrict__ extra,  // [B,N,DIM]
                 const float* __restrict__ w1,     // [129,128]
                 const float* __restrict__ w2p)    // [128,1]
{
    extern __shared__ __align__(16) float smem[];
    uint4* BF      = (uint4*)smem;                     // [128][20] uint4
    float* slices  = smem + BF_BYTES / 4;              // 16 warp-slices
    float* w2_s    = slices + ATTN_WARPS * SL_WORDS;
    float* w1r_s   = w2_s + 128;

    const int t = threadIdx.x, warp = t >> 5, lane = t & 31;
    const int g = lane >> 2, tc = lane & 3;

    // ---- one-time: W1 fragment table, fp16, ks-pairs packed ----
#pragma unroll
    for (int i = 0; i < 4; i++) {
        int idx = t + i * 512;                 // 2048 entries = d*16 + ks2*4 + tc
        int d = idx >> 4, rem = idx & 15, ks2 = rem >> 2, tcc = rem & 3;
        int jA = 32 * ks2 + 2 * tcc;           // ks = 2*ks2
        int jB = jA + 16;                      // ks = 2*ks2+1
        uint32_t b0A = packh(w1[jA * 128 + d],       w1[(jA + 1) * 128 + d]);
        uint32_t b1A = packh(w1[(jA + 8) * 128 + d], w1[(jA + 9) * 128 + d]);
        uint32_t b0B = packh(w1[jB * 128 + d],       w1[(jB + 1) * 128 + d]);
        uint32_t b1B = packh(w1[(jB + 8) * 128 + d], w1[(jB + 9) * 128 + d]);
        BF[d * BF_U4_STRIDE + ks2 * 4 + tcc] = make_uint4(b0A, b1A, b0B, b1B);
    }
    if (t < 128) { w2_s[t] = w2p[t]; w1r_s[t] = w1[128 * 128 + t]; }
    __syncthreads();

    float* sl = slices + warp * SL_WORDS;
    const uint32_t sa = (uint32_t)__cvta_generic_to_shared(sl);

    const int gw = blockIdx.x * ATTN_WARPS + warp;

    if (gw < BN_TOTAL) issue_bn(sa, nbrv, nbrw, extra, gw, lane);
    CP_COMMIT();

    for (int bn = gw; bn < BN_TOTAL; bn += TOTAL_WARPS) {
        CP_WAIT0();
        __syncwarp();

        const float* nb = sl;
        const float* ex = sl + SL_EXTRA;

        float acc[16][4];
#pragma unroll
        for (int nt = 0; nt < 16; nt++) {
            acc[nt][0] = 0.f; acc[nt][1] = 0.f; acc[nt][2] = 0.f; acc[nt][3] = 0.f;
        }

        const bool hasHi = (g < 4);            // rows g+8 valid only if < 12
#pragma unroll
        for (int ks2 = 0; ks2 < 4; ks2++) {
            uint32_t a[2][4];
#pragma unroll
            for (int s = 0; s < 2; s++) {
                const int jb = 32 * ks2 + 16 * s + 2 * tc;
                float2 e0 = *(const float2*)(ex + jb);
                float2 e1 = *(const float2*)(ex + jb + 8);
                float2 p00 = *(const float2*)(nb + g * SL_NBR_STRIDE + jb);
                float2 p01 = *(const float2*)(nb + g * SL_NBR_STRIDE + jb + 8);
                float2 p10 = make_float2(0.f, 0.f), p11 = make_float2(0.f, 0.f);
                if (hasHi) {
                    p10 = *(const float2*)(nb + (g + 8) * SL_NBR_STRIDE + jb);
                    p11 = *(const float2*)(nb + (g + 8) * SL_NBR_STRIDE + jb + 8);
                }
                a[s][0] = packh(e0.x * p00.x, e0.y * p00.y);
                a[s][1] = packh(e0.x * p10.x, e0.y * p10.y);
                a[s][2] = packh(e1.x * p01.x, e1.y * p01.y);
                a[s][3] = packh(e1.x * p11.x, e1.y * p11.y);
            }
            const uint4* brow = BF + ks2 * 4 + tc;
#pragma unroll
            for (int nt = 0; nt < 16; nt++) {
                uint4 b = brow[(nt * 8 + g) * BF_U4_STRIDE];
                mma16816(acc[nt], a[0][0], a[0][1], a[0][2], a[0][3], b.x, b.y);
                mma16816(acc[nt], a[1][0], a[1][1], a[1][2], a[1][3], b.z, b.w);
            }
        }

        // ---- epilogue: logits ----
        const float wg  = sl[SL_W + g];
        const float wg8 = sl[SL_W + g + 8];   // garbage for g>=4 -> rows discarded
        float pg = 0.f, pg8 = 0.f;
#pragma unroll
        for (int nt = 0; nt < 16; nt++) {
            int d0 = nt * 8 + 2 * tc;
            float2 w2v = *(const float2*)(w2_s + d0);
            float2 wrv = *(const float2*)(w1r_s + d0);
            float x;
            x = acc[nt][0] + wg  * wrv.x; pg  += w2v.x * ((x > 0.f) ? x : 0.2f * x);
            x = acc[nt][1] + wg  * wrv.y; pg  += w2v.y * ((x > 0.f) ? x : 0.2f * x);
            x = acc[nt][2] + wg8 * wrv.x; pg8 += w2v.x * ((x > 0.f) ? x : 0.2f * x);
            x = acc[nt][3] + wg8 * wrv.y; pg8 += w2v.y * ((x > 0.f) ? x : 0.2f * x);
        }
        pg  += __shfl_xor_sync(0xffffffffu, pg, 1);
        pg  += __shfl_xor_sync(0xffffffffu, pg, 2);
        pg8 += __shfl_xor_sync(0xffffffffu, pg8, 1);
        pg8 += __shfl_xor_sync(0xffffffffu, pg8, 2);
        if (tc == 0) { sl[SL_LG + g] = pg; sl[SL_LG + g + 8] = pg8; }
        __syncwarp();

        // ---- softmax over k=0..11 (all lanes redundantly) ----
        float lg[12];
        float m = -1e30f;
#pragma unroll
        for (int k = 0; k < 12; k++) { lg[k] = sl[SL_LG + k]; m = fmaxf(m, lg[k]); }
        float ssum = 0.f;
#pragma unroll
        for (int k = 0; k < 12; k++) { lg[k] = __expf(lg[k] - m); ssum += lg[k]; }
        const float inv = 1.0f / ssum;

        // ---- aggregation: lane covers d = lane*4..+3 (fp32 exact) ----
        float4 a4 = make_float4(0.f, 0.f, 0.f, 0.f);
#pragma unroll
        for (int k = 0; k < 12; k++) {
            float al = lg[k] * inv;
            float4 nv = *(const float4*)(nb + k * SL_NBR_STRIDE + lane * 4);
            a4.x = fmaf(al, nv.x, a4.x);
            a4.y = fmaf(al, nv.y, a4.y);
            a4.z = fmaf(al, nv.z, a4.z);
            a4.w = fmaf(al, nv.w, a4.w);
        }
        *(float4*)(g_agg + (size_t)bn * DIMc + lane * 4) = a4;

        __syncwarp();   // all lanes done reading before refill
        int bnN = bn + TOTAL_WARPS;
        if (bnN < BN_TOTAL) issue_bn(sa, nbrv, nbrw, extra, bnN, lane);
        CP_COMMIT();
    }
}

// =====================================================================
// Kernel 2: out = relu(concat(self, agg) @ W3) via fp16 1-term mma.
//   148 CTAs x 512 threads (16 warps = 4/SMSP). warp = (rowgroup rg,
//   colhalf ch): 16 rows, 64 cols (8 nt -> 32 acc regs). W3 table packs
//   ks-pairs per uint4 (stride 36, conflict-free). Warp pair (2rg,2rg+1)
//   stages rowgroup rg's x as fp16.   (unchanged from R10, 48.4us)
// =====================================================================
#define BF3_U4_STRIDE 36
#define BF3_BYTES     (128 * BF3_U4_STRIDE * 16)     // 73728
#define XH_STRIDE     132                            // u32 words per row
#define XH_WORDS      (16 * XH_STRIDE)               // per rowgroup
#define SMEM2_USED    (BF3_BYTES + 8 * XH_WORDS * 4) // 141312
#define SMEM2_BYTES   ((SMEM2_USED + 1023) & ~1023)  // 141312

__global__ __launch_bounds__(512, 1)
void out_kernel(const float* __restrict__ selfv,  // [B,N,DIM]
                const float* __restrict__ w3,     // [256,128]
                float* __restrict__ out)          // [B,N,DIM]
{
    extern __shared__ __align__(16) float smem[];
    uint4*    BF3 = (uint4*)smem;
    uint32_t* xh  = (uint32_t*)(smem + BF3_BYTES / 4);

    const int t = threadIdx.x, warp = t >> 5, lane = t & 31;
    const int g = lane >> 2, tc = lane & 3;
    const int rg = warp >> 1, ch = warp & 1;
    const int pairlane = t & 63;

    // ---- one-time: W3 fragment table (fp16, ks-pairs packed) ----
#pragma unroll
    for (int i = 0; i < 8; i++) {
        int idx = t + i * 512;                 // 4096 entries = d*32 + ks2*4 + tc
        int d = idx >> 5, rem = idx & 31, ks2 = rem >> 2, tcc = rem & 3;
        int jA = 32 * ks2 + 2 * tcc;           // ks = 2*ks2
        int jB = jA + 16;                      // ks = 2*ks2+1
        uint32_t b0A = packh(w3[jA * 128 + d],       w3[(jA + 1) * 128 + d]);
        uint32_t b1A = packh(w3[(jA + 8) * 128 + d], w3[(jA + 9) * 128 + d]);
        uint32_t b0B = packh(w3[jB * 128 + d],       w3[(jB + 1) * 128 + d]);
        uint32_t b1B = packh(w3[(jB + 8) * 128 + d], w3[(jB + 9) * 128 + d]);
        BF3[d * BF3_U4_STRIDE + ks2 * 4 + tcc] = make_uint4(b0A, b1A, b0B, b1B);
    }
    __syncthreads();

    uint32_t* xw = xh + rg * XH_WORDS;
    const int n_pass = BN_TOTAL / 128;        // 512

    for (int p = blockIdx.x; p < n_pass; p += gridDim.x) {
        const int row0 = p * 128 + rg * 16;    // this rowgroup's 16 rows

        // ---- stage x = concat(self, agg) as fp16 (warp pair, 64 lanes) ----
#pragma unroll
        for (int i = 0; i < 16; i++) {
            int idx = i * 64 + pairlane;
            int row = idx >> 6, f4 = idx & 63;
            const float4 v = (f4 < 32)
                ? *(const float4*)(selfv + (size_t)(row0 + row) * 128 + f4 * 4)
                : *(const float4*)(g_agg + (size_t)(row0 + row) * 128 + (f4 - 32) * 4);
            uint2 w2v;
            w2v.x = packh(v.x, v.y);
            w2v.y = packh(v.z, v.w);
            *(uint2*)(xw + row * XH_STRIDE + f4 * 2) = w2v;
        }
        __syncthreads();

        float acc[8][4];
#pragma unroll
        for (int nt = 0; nt < 8; nt++) {
            acc[nt][0] = 0.f; acc[nt][1] = 0.f; acc[nt][2] = 0.f; acc[nt][3] = 0.f;
        }

#pragma unroll
        for (int ks2 = 0; ks2 < 8; ks2++) {
            uint32_t a[2][4];
#pragma unroll
            for (int s = 0; s < 2; s++) {
                int ks = 2 * ks2 + s;
                a[s][0] = xw[g * XH_STRIDE + 8 * ks + tc];
                a[s][1] = xw[(g + 8) * XH_STRIDE + 8 * ks + tc];
                a[s][2] = xw[g * XH_STRIDE + 8 * ks + tc + 4];
                a[s][3] = xw[(g + 8) * XH_STRIDE + 8 * ks + tc + 4];
            }
            const uint4* brow = BF3 + ks2 * 4 + tc;
#pragma unroll
            for (int nt = 0; nt < 8; nt++) {
                uint4 b = brow[(ch * 64 + nt * 8 + g) * BF3_U4_STRIDE];
                mma16816(acc[nt], a[0][0], a[0][1], a[0][2], a[0][3], b.x, b.y);
                mma16816(acc[nt], a[1][0], a[1][1], a[1][2], a[1][3], b.z, b.w);
            }
        }

        // ---- epilogue: relu + store (warp's 64-col half) ----
#pragma unroll
        for (int nt = 0; nt < 8; nt++) {
            int d0 = ch * 64 + nt * 8 + 2 * tc;
            float2 v0 = make_float2(fmaxf(acc[nt][0], 0.f), fmaxf(acc[nt][1], 0.f));
            float2 v1 = make_float2(fmaxf(acc[nt][2], 0.f), fmaxf(acc[nt][3], 0.f));
            *(float2*)(out + (size_t)(row0 + g) * 128 + d0)     = v0;
            *(float2*)(out + (size_t)(row0 + g + 8) * 128 + d0) = v1;
        }
        __syncthreads();   // xw reuse next pass
    }
}

// =====================================================================
// Launch.  Inputs: 0 self, 1 neighbor_vector, 2 neighbor_weight,
//   3 extra_vector, 4 masks, 5 batch_size, 6 w_1, 7 w_2, 8 w_3
// =====================================================================
extern "C" void kernel_launch(void* const* d_in, const int* in_sizes, int n_in,
                              void* d_out, int out_size)
{
    const float* selfv = (const float*)d_in[0];
    const float* nbrv  = (const float*)d_in[1];
    const float* nbrw  = (const float*)d_in[2];
    const float* extra = (const float*)d_in[3];
    const float* w1    = (const float*)d_in[6];
    const float* w2    = (const float*)d_in[7];
    const float* w3    = (const float*)d_in[8];
    float* out = (float*)d_out;

    cudaFuncSetAttribute(attn_kernel, cudaFuncAttributeMaxDynamicSharedMemorySize,
                         SMEM1_BYTES);
    attn_kernel<<<ATTN_GRID, 512, SMEM1_BYTES>>>(nbrv, nbrw, extra, w1, w2);

    cudaFuncSetAttribute(out_kernel, cudaFuncAttributeMaxDynamicSharedMemorySize,
                         SMEM2_BYTES);
    out_kernel<<<148, 512, SMEM2_BYTES>>>(selfv, w3, out);
}